// round 7
// baseline (speedup 1.0000x reference)
#include <cuda_runtime.h>
#include <math.h>

#define BB 2048
#define MM 2048
#define HH 64
#define DD 64
#define VV 128
#define GG 32
#define L2E 1.4426950408889634f
#define SPLIT 2
#define MSL (MM / SPLIT)            // 1024 rows per CTA slice

// partial state per (b, slice): acc[64], sumP, maxS
__device__ float g_part[BB * SPLIT][DD + 2];

// ================= Kernel 1: streaming softmax partials =================
__global__ __launch_bounds__(256, 4) void memret_partial(
    const float* __restrict__ query,
    const float* __restrict__ memory,
    const float* __restrict__ Wq, const float* __restrict__ bq)
{
    const int bid  = blockIdx.x;
    const int b    = bid >> 1;
    const int mh   = bid & 1;        // which 1024-row slice
    const int tid  = threadIdx.x;
    const int lane = tid & 31;
    const int w    = tid >> 5;
    const int half = lane >> 4;
    const int sub  = lane & 15;

    __shared__ float sq[HH];
    __shared__ float qp[DD];
    __shared__ float accS[16][DD];
    __shared__ float mS[16], sS[16];

    // ---- q_proj * (1/sqrt(D)) * log2(e) ----
    if (tid < HH) sq[tid] = query[(size_t)b * HH + tid];
    __syncthreads();
    if (tid < DD) {
        float a = bq[tid];
        #pragma unroll
        for (int h = 0; h < HH; ++h) a = fmaf(sq[h], Wq[h * DD + tid], a);
        qp[tid] = a * (0.125f * L2E);
    }
    __syncthreads();

    const float4 qv = *reinterpret_cast<const float4*>(qp + sub * 4);
    const float4* mb4 = reinterpret_cast<const float4*>(
        memory + ((size_t)b * MM + (size_t)mh * MSL) * DD);

    float runM = -INFINITY, runS = 0.f;
    float4 acc = make_float4(0.f, 0.f, 0.f, 0.f);
    const int base = w * 32 + lane;

    float4 c0 = __ldcs(&mb4[base]);
    float4 c1 = __ldcs(&mb4[base + 256]);
    float4 c2 = __ldcs(&mb4[base + 512]);
    float4 c3 = __ldcs(&mb4[base + 768]);

    #pragma unroll 1
    for (int j = 0; j < MSL / 16 - 4; j += 4) {
        const int nb = (j + 4) * 256 + base;
        float4 n0 = __ldcs(&mb4[nb]);
        float4 n1 = __ldcs(&mb4[nb + 256]);
        float4 n2 = __ldcs(&mb4[nb + 512]);
        float4 n3 = __ldcs(&mb4[nb + 768]);

        float s0 = c0.x * qv.x; s0 = fmaf(c0.y, qv.y, s0); s0 = fmaf(c0.z, qv.z, s0); s0 = fmaf(c0.w, qv.w, s0);
        float s1 = c1.x * qv.x; s1 = fmaf(c1.y, qv.y, s1); s1 = fmaf(c1.z, qv.z, s1); s1 = fmaf(c1.w, qv.w, s1);
        float s2 = c2.x * qv.x; s2 = fmaf(c2.y, qv.y, s2); s2 = fmaf(c2.z, qv.z, s2); s2 = fmaf(c2.w, qv.w, s2);
        float s3 = c3.x * qv.x; s3 = fmaf(c3.y, qv.y, s3); s3 = fmaf(c3.z, qv.z, s3); s3 = fmaf(c3.w, qv.w, s3);

        #pragma unroll
        for (int off = 8; off; off >>= 1) {
            s0 += __shfl_xor_sync(0xffffffffu, s0, off);
            s1 += __shfl_xor_sync(0xffffffffu, s1, off);
            s2 += __shfl_xor_sync(0xffffffffu, s2, off);
            s3 += __shfl_xor_sync(0xffffffffu, s3, off);
        }

        float p0 = exp2f(s0), p1 = exp2f(s1), p2 = exp2f(s2), p3 = exp2f(s3);
        runM = fmaxf(runM, fmaxf(fmaxf(s0, s1), fmaxf(s2, s3)));
        runS += ((p0 + p1) + (p2 + p3));

        acc.x = fmaf(p0, c0.x, acc.x); acc.y = fmaf(p0, c0.y, acc.y);
        acc.z = fmaf(p0, c0.z, acc.z); acc.w = fmaf(p0, c0.w, acc.w);
        acc.x = fmaf(p1, c1.x, acc.x); acc.y = fmaf(p1, c1.y, acc.y);
        acc.z = fmaf(p1, c1.z, acc.z); acc.w = fmaf(p1, c1.w, acc.w);
        acc.x = fmaf(p2, c2.x, acc.x); acc.y = fmaf(p2, c2.y, acc.y);
        acc.z = fmaf(p2, c2.z, acc.z); acc.w = fmaf(p2, c2.w, acc.w);
        acc.x = fmaf(p3, c3.x, acc.x); acc.y = fmaf(p3, c3.y, acc.y);
        acc.z = fmaf(p3, c3.z, acc.z); acc.w = fmaf(p3, c3.w, acc.w);

        c0 = n0; c1 = n1; c2 = n2; c3 = n3;
    }
    {   // last group
        float s0 = c0.x * qv.x; s0 = fmaf(c0.y, qv.y, s0); s0 = fmaf(c0.z, qv.z, s0); s0 = fmaf(c0.w, qv.w, s0);
        float s1 = c1.x * qv.x; s1 = fmaf(c1.y, qv.y, s1); s1 = fmaf(c1.z, qv.z, s1); s1 = fmaf(c1.w, qv.w, s1);
        float s2 = c2.x * qv.x; s2 = fmaf(c2.y, qv.y, s2); s2 = fmaf(c2.z, qv.z, s2); s2 = fmaf(c2.w, qv.w, s2);
        float s3 = c3.x * qv.x; s3 = fmaf(c3.y, qv.y, s3); s3 = fmaf(c3.z, qv.z, s3); s3 = fmaf(c3.w, qv.w, s3);
        #pragma unroll
        for (int off = 8; off; off >>= 1) {
            s0 += __shfl_xor_sync(0xffffffffu, s0, off);
            s1 += __shfl_xor_sync(0xffffffffu, s1, off);
            s2 += __shfl_xor_sync(0xffffffffu, s2, off);
            s3 += __shfl_xor_sync(0xffffffffu, s3, off);
        }
        float p0 = exp2f(s0), p1 = exp2f(s1), p2 = exp2f(s2), p3 = exp2f(s3);
        runM = fmaxf(runM, fmaxf(fmaxf(s0, s1), fmaxf(s2, s3)));
        runS += ((p0 + p1) + (p2 + p3));
        acc.x = fmaf(p0, c0.x, acc.x); acc.y = fmaf(p0, c0.y, acc.y);
        acc.z = fmaf(p0, c0.z, acc.z); acc.w = fmaf(p0, c0.w, acc.w);
        acc.x = fmaf(p1, c1.x, acc.x); acc.y = fmaf(p1, c1.y, acc.y);
        acc.z = fmaf(p1, c1.z, acc.z); acc.w = fmaf(p1, c1.w, acc.w);
        acc.x = fmaf(p2, c2.x, acc.x); acc.y = fmaf(p2, c2.y, acc.y);
        acc.z = fmaf(p2, c2.z, acc.z); acc.w = fmaf(p2, c2.w, acc.w);
        acc.x = fmaf(p3, c3.x, acc.x); acc.y = fmaf(p3, c3.y, acc.y);
        acc.z = fmaf(p3, c3.z, acc.z); acc.w = fmaf(p3, c3.w, acc.w);
    }

    const int si = 2 * w + half;
    *reinterpret_cast<float4*>(&accS[si][sub * 4]) = acc;
    if (sub == 0) { mS[si] = runM; sS[si] = runS; }
    __syncthreads();

    // ---- combine 16 sub-states, write partial record ----
    if (tid < DD) {
        float r = 0.f;
        #pragma unroll
        for (int i = 0; i < 16; ++i) r += accS[i][tid];
        g_part[bid][tid] = r;
    } else if (tid == DD) {
        float d = 0.f;
        #pragma unroll
        for (int i = 0; i < 16; ++i) d += sS[i];
        g_part[bid][DD] = d;
    } else if (tid == DD + 1) {
        float gM = mS[0];
        #pragma unroll
        for (int i = 1; i < 16; ++i) gM = fmaxf(gM, mS[i]);
        g_part[bid][DD + 1] = gM;
    }
}

// ================= Kernel 2: combine + epilogue (8 batches/block) =======
#define BPB 8
__global__ __launch_bounds__(256) void memret_epilogue(
    const float* __restrict__ query,
    const float* __restrict__ Wo, const float* __restrict__ bo,
    const float* __restrict__ Wg1, const float* __restrict__ bg1,
    const float* __restrict__ Wg2, const float* __restrict__ bg2,
    const float* __restrict__ null_vec,
    const float* __restrict__ Wc, const float* __restrict__ bc,
    float* __restrict__ out_logits, float* __restrict__ out_gate)
{
    const int tid  = threadIdx.x;
    const int lane = tid & 31;
    const int w    = tid >> 5;

    __shared__ float sq[HH];
    __shared__ float sret[DD];
    __shared__ float srh[HH];
    __shared__ float sout[HH];
    __shared__ float sgate;
    __shared__ float smax;

    for (int bs = 0; bs < BPB; ++bs) {
        const int b = blockIdx.x * BPB + bs;

        if (tid < HH) sq[tid] = query[(size_t)b * HH + tid];
        if (tid < DD) {
            float r = g_part[2 * b][tid] + g_part[2 * b + 1][tid];
            float d = g_part[2 * b][DD]  + g_part[2 * b + 1][DD];
            sret[tid] = r / d;
            if (tid == 0)
                smax = fmaxf(g_part[2 * b][DD + 1], g_part[2 * b + 1][DD + 1]) * (1.0f / L2E);
        }
        __syncthreads();

        // gate MLP (warp 0)
        if (w == 0) {
            float hv = bg1[lane];
            #pragma unroll
            for (int h = 0; h < HH; ++h) hv = fmaf(sq[h], Wg1[h * GG + lane], hv);
            hv = fmaf(smax, Wg1[HH * GG + lane], hv);
            hv = fmaxf(hv, 0.f) * Wg2[lane];
            #pragma unroll
            for (int off = 16; off; off >>= 1)
                hv += __shfl_xor_sync(0xffffffffu, hv, off);
            if (lane == 0) {
                float g = 1.f / (1.f + expf(-(hv + bg2[0])));
                sgate = g;
                out_gate[b] = g;
            }
        }
        // retrieved @ Wo + bo (warps 2,3)
        if (tid >= 64 && tid < 128) {
            int h = tid - 64;
            float a = bo[h];
            #pragma unroll
            for (int d = 0; d < DD; ++d) a = fmaf(sret[d], Wo[d * HH + h], a);
            srh[h] = a;
        }
        __syncthreads();

        if (tid < HH) {
            float g = sgate;
            sout[tid] = fmaf(g, srh[tid], (1.f - g) * null_vec[tid]);
        }
        __syncthreads();

        if (tid < VV) {
            float a = bc[tid];
            #pragma unroll
            for (int h = 0; h < HH; ++h) a = fmaf(sout[h], Wc[h * VV + tid], a);
            out_logits[(size_t)b * VV + tid] = a;
        }
        __syncthreads();
    }
}

extern "C" void kernel_launch(void* const* d_in, const int* in_sizes, int n_in,
                              void* d_out, int out_size)
{
    const float* query    = (const float*)d_in[0];
    const float* memory   = (const float*)d_in[1];
    const float* Wq       = (const float*)d_in[2];
    const float* bq       = (const float*)d_in[3];
    const float* Wo       = (const float*)d_in[4];
    const float* bo       = (const float*)d_in[5];
    const float* Wg1      = (const float*)d_in[6];
    const float* bg1      = (const float*)d_in[7];
    const float* Wg2      = (const float*)d_in[8];
    const float* bg2      = (const float*)d_in[9];
    const float* null_vec = (const float*)d_in[10];
    const float* Wc       = (const float*)d_in[11];
    const float* bc       = (const float*)d_in[12];

    float* out_logits = (float*)d_out;                 // (B, V)
    float* out_gate   = out_logits + (size_t)BB * VV;  // (B,)

    memret_partial<<<BB * SPLIT, 256>>>(query, memory, Wq, bq);
    memret_epilogue<<<BB / BPB, 256>>>(query, Wo, bo, Wg1, bg1, Wg2, bg2,
                                       null_vec, Wc, bc, out_logits, out_gate);
}

// round 9
// speedup vs baseline: 1.0735x; 1.0735x over previous
#include <cuda_runtime.h>
#include <math.h>

#define BB 2048
#define MM 2048
#define HH 64
#define DD 64
#define VV 128
#define GG 32
#define L2E 1.4426950408889634f
#define SPLIT 2
#define MSL (MM / SPLIT)            // 1024 rows per CTA slice

// partial state per (b, slice): acc[64], sumP, maxS
__device__ float g_part[BB * SPLIT][DD + 2];

// ================= Kernel 1: streaming softmax partials =================
__global__ __launch_bounds__(256, 4) void memret_partial(
    const float* __restrict__ query,
    const float* __restrict__ memory,
    const float* __restrict__ Wq, const float* __restrict__ bq)
{
    const int bid  = blockIdx.x;
    const int b    = bid >> 1;
    const int mh   = bid & 1;        // which 1024-row slice
    const int tid  = threadIdx.x;
    const int lane = tid & 31;
    const int w    = tid >> 5;
    const int half = lane >> 4;
    const int sub  = lane & 15;

    __shared__ float sq[HH];
    __shared__ float qp[DD];
    __shared__ float accS[16][DD];
    __shared__ float mS[16], sS[16];

    // ---- q_proj * (1/sqrt(D)) * log2(e) ----
    if (tid < HH) sq[tid] = query[(size_t)b * HH + tid];
    __syncthreads();
    if (tid < DD) {
        float a = bq[tid];
        #pragma unroll
        for (int h = 0; h < HH; ++h) a = fmaf(sq[h], Wq[h * DD + tid], a);
        qp[tid] = a * (0.125f * L2E);
    }
    __syncthreads();

    const float4 qv = *reinterpret_cast<const float4*>(qp + sub * 4);
    const float4* mb4 = reinterpret_cast<const float4*>(
        memory + ((size_t)b * MM + (size_t)mh * MSL) * DD);

    float runM = -INFINITY, runS = 0.f;
    float4 acc = make_float4(0.f, 0.f, 0.f, 0.f);
    const int base = w * 32 + lane;

    float4 c0 = __ldcs(&mb4[base]);
    float4 c1 = __ldcs(&mb4[base + 256]);
    float4 c2 = __ldcs(&mb4[base + 512]);
    float4 c3 = __ldcs(&mb4[base + 768]);

    #pragma unroll 1
    for (int j = 0; j < MSL / 16 - 4; j += 4) {
        const int nb = (j + 4) * 256 + base;
        float4 n0 = __ldcs(&mb4[nb]);
        float4 n1 = __ldcs(&mb4[nb + 256]);
        float4 n2 = __ldcs(&mb4[nb + 512]);
        float4 n3 = __ldcs(&mb4[nb + 768]);

        float s0 = c0.x * qv.x; s0 = fmaf(c0.y, qv.y, s0); s0 = fmaf(c0.z, qv.z, s0); s0 = fmaf(c0.w, qv.w, s0);
        float s1 = c1.x * qv.x; s1 = fmaf(c1.y, qv.y, s1); s1 = fmaf(c1.z, qv.z, s1); s1 = fmaf(c1.w, qv.w, s1);
        float s2 = c2.x * qv.x; s2 = fmaf(c2.y, qv.y, s2); s2 = fmaf(c2.z, qv.z, s2); s2 = fmaf(c2.w, qv.w, s2);
        float s3 = c3.x * qv.x; s3 = fmaf(c3.y, qv.y, s3); s3 = fmaf(c3.z, qv.z, s3); s3 = fmaf(c3.w, qv.w, s3);

        #pragma unroll
        for (int off = 8; off; off >>= 1) {
            s0 += __shfl_xor_sync(0xffffffffu, s0, off);
            s1 += __shfl_xor_sync(0xffffffffu, s1, off);
            s2 += __shfl_xor_sync(0xffffffffu, s2, off);
            s3 += __shfl_xor_sync(0xffffffffu, s3, off);
        }

        float p0 = exp2f(s0), p1 = exp2f(s1), p2 = exp2f(s2), p3 = exp2f(s3);
        runM = fmaxf(runM, fmaxf(fmaxf(s0, s1), fmaxf(s2, s3)));
        runS += ((p0 + p1) + (p2 + p3));

        acc.x = fmaf(p0, c0.x, acc.x); acc.y = fmaf(p0, c0.y, acc.y);
        acc.z = fmaf(p0, c0.z, acc.z); acc.w = fmaf(p0, c0.w, acc.w);
        acc.x = fmaf(p1, c1.x, acc.x); acc.y = fmaf(p1, c1.y, acc.y);
        acc.z = fmaf(p1, c1.z, acc.z); acc.w = fmaf(p1, c1.w, acc.w);
        acc.x = fmaf(p2, c2.x, acc.x); acc.y = fmaf(p2, c2.y, acc.y);
        acc.z = fmaf(p2, c2.z, acc.z); acc.w = fmaf(p2, c2.w, acc.w);
        acc.x = fmaf(p3, c3.x, acc.x); acc.y = fmaf(p3, c3.y, acc.y);
        acc.z = fmaf(p3, c3.z, acc.z); acc.w = fmaf(p3, c3.w, acc.w);

        c0 = n0; c1 = n1; c2 = n2; c3 = n3;
    }
    {   // last group
        float s0 = c0.x * qv.x; s0 = fmaf(c0.y, qv.y, s0); s0 = fmaf(c0.z, qv.z, s0); s0 = fmaf(c0.w, qv.w, s0);
        float s1 = c1.x * qv.x; s1 = fmaf(c1.y, qv.y, s1); s1 = fmaf(c1.z, qv.z, s1); s1 = fmaf(c1.w, qv.w, s1);
        float s2 = c2.x * qv.x; s2 = fmaf(c2.y, qv.y, s2); s2 = fmaf(c2.z, qv.z, s2); s2 = fmaf(c2.w, qv.w, s2);
        float s3 = c3.x * qv.x; s3 = fmaf(c3.y, qv.y, s3); s3 = fmaf(c3.z, qv.z, s3); s3 = fmaf(c3.w, qv.w, s3);
        #pragma unroll
        for (int off = 8; off; off >>= 1) {
            s0 += __shfl_xor_sync(0xffffffffu, s0, off);
            s1 += __shfl_xor_sync(0xffffffffu, s1, off);
            s2 += __shfl_xor_sync(0xffffffffu, s2, off);
            s3 += __shfl_xor_sync(0xffffffffu, s3, off);
        }
        float p0 = exp2f(s0), p1 = exp2f(s1), p2 = exp2f(s2), p3 = exp2f(s3);
        runM = fmaxf(runM, fmaxf(fmaxf(s0, s1), fmaxf(s2, s3)));
        runS += ((p0 + p1) + (p2 + p3));
        acc.x = fmaf(p0, c0.x, acc.x); acc.y = fmaf(p0, c0.y, acc.y);
        acc.z = fmaf(p0, c0.z, acc.z); acc.w = fmaf(p0, c0.w, acc.w);
        acc.x = fmaf(p1, c1.x, acc.x); acc.y = fmaf(p1, c1.y, acc.y);
        acc.z = fmaf(p1, c1.z, acc.z); acc.w = fmaf(p1, c1.w, acc.w);
        acc.x = fmaf(p2, c2.x, acc.x); acc.y = fmaf(p2, c2.y, acc.y);
        acc.z = fmaf(p2, c2.z, acc.z); acc.w = fmaf(p2, c2.w, acc.w);
        acc.x = fmaf(p3, c3.x, acc.x); acc.y = fmaf(p3, c3.y, acc.y);
        acc.z = fmaf(p3, c3.z, acc.z); acc.w = fmaf(p3, c3.w, acc.w);
    }

    const int si = 2 * w + half;
    *reinterpret_cast<float4*>(&accS[si][sub * 4]) = acc;
    if (sub == 0) { mS[si] = runM; sS[si] = runS; }
    __syncthreads();

    // ---- combine 16 sub-states, write partial record ----
    if (tid < DD) {
        float r = 0.f;
        #pragma unroll
        for (int i = 0; i < 16; ++i) r += accS[i][tid];
        g_part[bid][tid] = r;
    } else if (tid == DD) {
        float d = 0.f;
        #pragma unroll
        for (int i = 0; i < 16; ++i) d += sS[i];
        g_part[bid][DD] = d;
    } else if (tid == DD + 1) {
        float gM = mS[0];
        #pragma unroll
        for (int i = 1; i < 16; ++i) gM = fmaxf(gM, mS[i]);
        g_part[bid][DD + 1] = gM;
    }
}

// ======= Kernel 2: combine + epilogue — one 128-thread CTA per batch =====
__global__ __launch_bounds__(128) void memret_epilogue(
    const float* __restrict__ query,
    const float* __restrict__ Wo, const float* __restrict__ bo,
    const float* __restrict__ Wg1, const float* __restrict__ bg1,
    const float* __restrict__ Wg2, const float* __restrict__ bg2,
    const float* __restrict__ null_vec,
    const float* __restrict__ Wc, const float* __restrict__ bc,
    float* __restrict__ out_logits, float* __restrict__ out_gate)
{
    const int b    = blockIdx.x;
    const int tid  = threadIdx.x;
    const int lane = tid & 31;
    const int w    = tid >> 5;

    __shared__ float sq[HH];
    __shared__ float sret[DD];
    __shared__ float srh[HH];
    __shared__ float sout[HH];
    __shared__ float sgate;
    __shared__ float smax;

    // phase A: warps 0-1 load query; warps 2-3 combine partials
    if (tid < HH) {
        sq[tid] = query[(size_t)b * HH + tid];
    } else {
        int d = tid - 64;
        float r   = g_part[2 * b][d]  + g_part[2 * b + 1][d];
        float den = g_part[2 * b][DD] + g_part[2 * b + 1][DD];
        sret[d] = r / den;
        if (d == 0)
            smax = fmaxf(g_part[2 * b][DD + 1], g_part[2 * b + 1][DD + 1]) * (1.0f / L2E);
    }
    __syncthreads();

    // phase B: warp 0 -> gate MLP;  warps 2-3 -> retrieved @ Wo + bo
    if (w == 0) {
        float hv = bg1[lane];
        #pragma unroll
        for (int h = 0; h < HH; ++h) hv = fmaf(sq[h], Wg1[h * GG + lane], hv);
        hv = fmaf(smax, Wg1[HH * GG + lane], hv);
        hv = fmaxf(hv, 0.f) * Wg2[lane];
        #pragma unroll
        for (int off = 16; off; off >>= 1)
            hv += __shfl_xor_sync(0xffffffffu, hv, off);
        if (lane == 0) {
            float g = 1.f / (1.f + expf(-(hv + bg2[0])));
            sgate = g;
            out_gate[b] = g;
        }
    } else if (tid >= 64) {
        int h = tid - 64;
        float a = bo[h];
        #pragma unroll
        for (int d = 0; d < DD; ++d) a = fmaf(sret[d], Wo[d * HH + h], a);
        srh[h] = a;
    }
    __syncthreads();

    // phase C: gate mix
    if (tid < HH) {
        float g = sgate;
        sout[tid] = fmaf(g, srh[tid], (1.f - g) * null_vec[tid]);
    }
    __syncthreads();

    // phase D: logits = out @ Wc + bc  (all 128 threads, one V column each)
    {
        float a = bc[tid];
        #pragma unroll
        for (int h = 0; h < HH; ++h) a = fmaf(sout[h], Wc[h * VV + tid], a);
        out_logits[(size_t)b * VV + tid] = a;
    }
}

extern "C" void kernel_launch(void* const* d_in, const int* in_sizes, int n_in,
                              void* d_out, int out_size)
{
    const float* query    = (const float*)d_in[0];
    const float* memory   = (const float*)d_in[1];
    const float* Wq       = (const float*)d_in[2];
    const float* bq       = (const float*)d_in[3];
    const float* Wo       = (const float*)d_in[4];
    const float* bo       = (const float*)d_in[5];
    const float* Wg1      = (const float*)d_in[6];
    const float* bg1      = (const float*)d_in[7];
    const float* Wg2      = (const float*)d_in[8];
    const float* bg2      = (const float*)d_in[9];
    const float* null_vec = (const float*)d_in[10];
    const float* Wc       = (const float*)d_in[11];
    const float* bc       = (const float*)d_in[12];

    float* out_logits = (float*)d_out;                 // (B, V)
    float* out_gate   = out_logits + (size_t)BB * VV;  // (B,)

    memret_partial<<<BB * SPLIT, 256>>>(query, memory, Wq, bq);
    memret_epilogue<<<BB, 128>>>(query, Wo, bo, Wg1, bg1, Wg2, bg2,
                                 null_vec, Wc, bc, out_logits, out_gate);
}